// round 8
// baseline (speedup 1.0000x reference)
#include <cuda_runtime.h>
#include <cuda_fp16.h>
#include <cstdint>

#define T_   1024
#define H_   1024
#define E_   16
#define I_   512      // MOE_INTER
#define IS_  1024     // SHARED_INTER
#define GUW_ 2048     // 2*SHARED_INTER

// ---------------- scratch (device globals; no allocs) ----------------
__device__ int    g_counts[E_];
__device__ int    g_tok[E_ * T_];
__device__ float  g_wt[E_ * T_];
__device__ __half g_h[(size_t)E_ * T_ * I_];   // routed intermediate (fp16)
__device__ __half g_hs[(size_t)T_ * IS_];      // shared-expert intermediate (fp16)

// ---------------- helpers ----------------
__device__ __forceinline__ float silu_mul(float g, float u) {
    return (g / (1.f + __expf(-g))) * u;
}
__device__ __forceinline__ uint32_t pack2(float a, float b) {
    __half2 h = __floats2half2_rn(a, b);
    return *reinterpret_cast<uint32_t*>(&h);
}
// m16n8k16 fp16 MMA, fp32 accum. A row-major, B col-major (k-contig per n)
__device__ __forceinline__ void mma16(float* d, const uint32_t* a, const uint32_t* b) {
    asm volatile(
        "mma.sync.aligned.m16n8k16.row.col.f32.f16.f16.f32 "
        "{%0,%1,%2,%3}, {%4,%5,%6,%7}, {%8,%9}, {%0,%1,%2,%3};"
        : "+f"(d[0]), "+f"(d[1]), "+f"(d[2]), "+f"(d[3])
        : "r"(a[0]), "r"(a[1]), "r"(a[2]), "r"(a[3]), "r"(b[0]), "r"(b[1]));
}

#define SAH 40                   // smem row stride in halves (80B, conflict-free)
#define A_SZH   (128 * SAH)      // A stage: 128 rows x 32 k halves
#define B64_SZH (64 * SAH)
#define B128_SZH (128 * SAH)

// ---------------- router ----------------
__global__ void zero_counts_kernel() {
    if (threadIdx.x < E_) g_counts[threadIdx.x] = 0;
}

__global__ void router_kernel(const float* __restrict__ x,
                              const float* __restrict__ rw) {
    __shared__ float sx[H_];
    __shared__ float slog[E_];
    int t = blockIdx.x;
    for (int i = threadIdx.x; i < H_; i += blockDim.x) sx[i] = x[(size_t)t * H_ + i];
    __syncthreads();
    int e = threadIdx.x >> 4, lane = threadIdx.x & 15;
    float s = 0.f;
    const float* w = rw + (size_t)e * H_;
    for (int i = lane; i < H_; i += 16) s += sx[i] * w[i];
    #pragma unroll
    for (int off = 8; off; off >>= 1) s += __shfl_down_sync(0xffffffffu, s, off, 16);
    if (lane == 0) slog[e] = s;
    __syncthreads();
    if (threadIdx.x == 0) {
        float l[E_];
        #pragma unroll
        for (int i = 0; i < E_; i++) l[i] = slog[i];
        int idx[4]; float lv[4]; bool used[E_];
        #pragma unroll
        for (int i = 0; i < E_; i++) used[i] = false;
        for (int k = 0; k < 4; k++) {      // top-4 of logits == top-4 of probs
            int bi = -1; float bv = -1e30f;
            for (int i = 0; i < E_; i++)
                if (!used[i] && l[i] > bv) { bv = l[i]; bi = i; }
            used[bi] = true; idx[k] = bi; lv[k] = bv;
        }
        float m = lv[0], ws[4], sum = 0.f;  // softmax denom cancels under top-k norm
        for (int k = 0; k < 4; k++) { ws[k] = __expf(lv[k] - m); sum += ws[k]; }
        float inv = 1.f / sum;
        for (int k = 0; k < 4; k++) {
            int pos = atomicAdd(&g_counts[idx[k]], 1);
            g_tok[idx[k] * T_ + pos] = t;
            g_wt[idx[k] * T_ + pos]  = ws[k] * inv;
        }
    }
}

// =====================================================================
// GEMM1 (fp16 m16n8k16): h = silu(A Wg) * (A Wu)
// BM=128, BN=64 (dual g/u), BK=32, 8 warps, warp tile 32x32 (x2 matrices)
// =====================================================================
__global__ __launch_bounds__(256)
void gemm1_mma(const float* __restrict__ x,
               const float* __restrict__ wg,
               const float* __restrict__ wu,
               const float* __restrict__ wgu) {
    extern __shared__ __half sh[];
    __half* As = sh;                    // [2][A_SZH]
    __half* Bg = sh + 2 * A_SZH;        // [2][B64_SZH]
    __half* Bu = Bg + 2 * B64_SZH;      // [2][B64_SZH]
    int* rows_s = (int*)(Bu + 2 * B64_SZH);

    int z = blockIdx.z, cx = blockIdx.x, row0 = blockIdx.y * 128;
    int cnt, e; const float *Bgp, *Bup; long ldb; __half* hout; int ldo;
    if (z == 0) {
        e = -1; cnt = T_;
        int c0 = cx * 64;
        Bgp = wgu + c0; Bup = wgu + IS_ + c0; ldb = GUW_;
        hout = g_hs + c0; ldo = IS_;
    } else {
        e = z - 1;
        if (cx >= I_ / 64) return;
        cnt = g_counts[e];
        if (row0 >= cnt) return;
        int c0 = cx * 64;
        size_t wo = (size_t)e * H_ * I_ + c0;
        Bgp = wg + wo; Bup = wu + wo; ldb = I_;
        hout = g_h + (size_t)e * T_ * I_ + c0; ldo = I_;
    }
    if (row0 >= cnt) return;

    int tid = threadIdx.x;
    if (tid < 128) {
        int r = row0 + tid;
        rows_s[tid] = (z == 0) ? r : ((r < cnt) ? g_tok[e * T_ + r] : -1);
    }
    __syncthreads();

    // loader roles
    int arow = tid & 127, akc = (tid >> 7) * 16;       // A: row, 16 k per thread
    int tr = rows_s[arow];
    const float* agf = x + (size_t)(tr < 0 ? 0 : tr) * H_ + akc;
    int bkk = tid & 31, bgrp = tid >> 5;               // B: k-row, n-group
    int bn0 = (bgrp & 3) * 16;
    const float* bbase = ((bgrp < 4) ? Bgp : Bup) + (size_t)bkk * ldb + bn0;
    __half* bsm = (bgrp < 4) ? Bg : Bu;

    int lane = tid & 31, wid = tid >> 5, gid = lane >> 2, t4 = lane & 3;
    int wm = wid & 3, wn = wid >> 2;

    float accg[2][4][4] = {}, accu[2][4][4] = {};
    float4 pa[4], pb[4];
    #pragma unroll
    for (int j = 0; j < 4; j++) pa[j] = (tr >= 0) ? *(const float4*)(agf + j * 4)
                                                  : make_float4(0.f, 0.f, 0.f, 0.f);
    #pragma unroll
    for (int j = 0; j < 4; j++) pb[j] = *(const float4*)(bbase + j * 4);

    const int NIT = H_ / 32;
    for (int it = 0; it < NIT; ++it) {
        int s = it & 1;
        // ---- STS (cvt to fp16)
        {
            __half* a = As + s * A_SZH;
            uint32_t hh[8];
            #pragma unroll
            for (int j = 0; j < 4; j++) {
                hh[2 * j]     = pack2(pa[j].x, pa[j].y);
                hh[2 * j + 1] = pack2(pa[j].z, pa[j].w);
            }
            uint4* dst = (uint4*)(a + arow * SAH + akc);
            dst[0] = make_uint4(hh[0], hh[1], hh[2], hh[3]);
            dst[1] = make_uint4(hh[4], hh[5], hh[6], hh[7]);

            __half* b = bsm + s * B64_SZH;
            #pragma unroll
            for (int j = 0; j < 4; j++) {
                float4 v = pb[j]; int n = bn0 + j * 4;
                b[(n + 0) * SAH + bkk] = __float2half_rn(v.x);
                b[(n + 1) * SAH + bkk] = __float2half_rn(v.y);
                b[(n + 2) * SAH + bkk] = __float2half_rn(v.z);
                b[(n + 3) * SAH + bkk] = __float2half_rn(v.w);
            }
        }
        __syncthreads();
        // ---- prefetch next tile (overlaps mma phase)
        if (it + 1 < NIT) {
            const float* ap = agf + (it + 1) * 32;
            #pragma unroll
            for (int j = 0; j < 4; j++) pa[j] = (tr >= 0) ? *(const float4*)(ap + j * 4)
                                                          : make_float4(0.f, 0.f, 0.f, 0.f);
            const float* bp = bbase + (size_t)(it + 1) * 32 * ldb;
            #pragma unroll
            for (int j = 0; j < 4; j++) pb[j] = *(const float4*)(bp + j * 4);
        }
        // ---- mma phase (scalar half2 fragment loads)
        {
            const __half* a  = As + s * A_SZH;
            const __half* bg = Bg + s * B64_SZH;
            const __half* bu = Bu + s * B64_SZH;
            #pragma unroll
            for (int kb = 0; kb < 32; kb += 16) {
                uint32_t af[2][4];
                #pragma unroll
                for (int mi = 0; mi < 2; mi++) {
                    int rm = wm * 32 + mi * 16 + gid;
                    af[mi][0] = *(const uint32_t*)(a + rm * SAH + kb + 2 * t4);
                    af[mi][1] = *(const uint32_t*)(a + (rm + 8) * SAH + kb + 2 * t4);
                    af[mi][2] = *(const uint32_t*)(a + rm * SAH + kb + 8 + 2 * t4);
                    af[mi][3] = *(const uint32_t*)(a + (rm + 8) * SAH + kb + 8 + 2 * t4);
                }
                #pragma unroll
                for (int ni = 0; ni < 4; ni++) {
                    int n = wn * 32 + ni * 8 + gid;
                    uint32_t bfg[2] = {*(const uint32_t*)(bg + n * SAH + kb + 2 * t4),
                                       *(const uint32_t*)(bg + n * SAH + kb + 8 + 2 * t4)};
                    uint32_t bfu[2] = {*(const uint32_t*)(bu + n * SAH + kb + 2 * t4),
                                       *(const uint32_t*)(bu + n * SAH + kb + 8 + 2 * t4)};
                    #pragma unroll
                    for (int mi = 0; mi < 2; mi++) {
                        mma16(accg[mi][ni], af[mi], bfg);
                        mma16(accu[mi][ni], af[mi], bfu);
                    }
                }
            }
        }
        __syncthreads();
    }

    // ---- epilogue: silu(g)*u, half2 stores
    #pragma unroll
    for (int mi = 0; mi < 2; mi++) {
        #pragma unroll
        for (int ni = 0; ni < 4; ni++) {
            int rb = row0 + wm * 32 + mi * 16 + gid;
            int c  = wn * 32 + ni * 8 + t4 * 2;
            if (rb < cnt) {
                *reinterpret_cast<__half2*>(hout + (size_t)rb * ldo + c) =
                    __floats2half2_rn(silu_mul(accg[mi][ni][0], accu[mi][ni][0]),
                                      silu_mul(accg[mi][ni][1], accu[mi][ni][1]));
            }
            if (rb + 8 < cnt) {
                *reinterpret_cast<__half2*>(hout + (size_t)(rb + 8) * ldo + c) =
                    __floats2half2_rn(silu_mul(accg[mi][ni][2], accu[mi][ni][2]),
                                      silu_mul(accg[mi][ni][3], accu[mi][ni][3]));
            }
        }
    }
}

// =====================================================================
// GEMM2 (fp16 m16n8k16): out += w * (h Wdown)
// BM=128, BN=128, BK=32, 8 warps, warp tile 32x64
// =====================================================================
__global__ __launch_bounds__(256)
void gemm2_mma(const float* __restrict__ wd,
               const float* __restrict__ wsd,
               float* __restrict__ out) {
    extern __shared__ __half sh[];
    __half* As = sh;                    // [2][A_SZH]
    __half* Bs = sh + 2 * A_SZH;        // [2][B128_SZH]

    int z = blockIdx.z, col0 = blockIdx.x * 128, row0 = blockIdx.y * 128;
    int cnt, e, K; const __half* Ap; const float* Bp; long lda;
    if (z == 0) {
        e = -1; cnt = T_; K = IS_;
        Ap = g_hs; lda = IS_;
        Bp = wsd + col0;
    } else {
        e = z - 1; cnt = g_counts[e]; K = I_;
        if (row0 >= cnt) return;
        Ap = g_h + (size_t)e * T_ * I_; lda = I_;
        Bp = wd + (size_t)e * I_ * H_ + col0;
    }
    if (row0 >= cnt) return;

    int tid = threadIdx.x;
    int arow = tid & 127, akc = (tid >> 7) * 16;      // 16 halves per thread
    int ar = row0 + arow;
    bool aok = (ar < cnt);
    const __half* agf = Ap + (size_t)ar * lda + akc;
    int bkk = tid & 31, bn0 = (tid >> 5) * 16;
    const float* bbase = Bp + (size_t)bkk * H_ + bn0;

    int lane = tid & 31, wid = tid >> 5, gid = lane >> 2, t4 = lane & 3;
    int wm = wid & 3, wn = wid >> 2;

    float acc[2][8][4] = {};
    uint4 pa0, pa1; float4 pb[4];
    const uint4 z4 = make_uint4(0, 0, 0, 0);
    pa0 = aok ? ((const uint4*)agf)[0] : z4;
    pa1 = aok ? ((const uint4*)agf)[1] : z4;
    #pragma unroll
    for (int j = 0; j < 4; j++) pb[j] = *(const float4*)(bbase + j * 4);

    const int NIT = K / 32;
    for (int it = 0; it < NIT; ++it) {
        int s = it & 1;
        // ---- STS
        {
            __half* a = As + s * A_SZH;
            uint4* dst = (uint4*)(a + arow * SAH + akc);
            dst[0] = pa0; dst[1] = pa1;

            __half* b = Bs + s * B128_SZH;
            #pragma unroll
            for (int j = 0; j < 4; j++) {
                float4 v = pb[j]; int n = bn0 + j * 4;
                b[(n + 0) * SAH + bkk] = __float2half_rn(v.x);
                b[(n + 1) * SAH + bkk] = __float2half_rn(v.y);
                b[(n + 2) * SAH + bkk] = __float2half_rn(v.z);
                b[(n + 3) * SAH + bkk] = __float2half_rn(v.w);
            }
        }
        __syncthreads();
        // ---- prefetch next
        if (it + 1 < NIT) {
            const __half* ap = agf + (it + 1) * 32;
            pa0 = aok ? ((const uint4*)ap)[0] : z4;
            pa1 = aok ? ((const uint4*)ap)[1] : z4;
            const float* bp = bbase + (size_t)(it + 1) * 32 * H_;
            #pragma unroll
            for (int j = 0; j < 4; j++) pb[j] = *(const float4*)(bp + j * 4);
        }
        // ---- mma phase
        {
            const __half* a = As + s * A_SZH;
            const __half* b = Bs + s * B128_SZH;
            #pragma unroll
            for (int kb = 0; kb < 32; kb += 16) {
                uint32_t af[2][4], bf[8][2];
                #pragma unroll
                for (int mi = 0; mi < 2; mi++) {
                    int rm = wm * 32 + mi * 16 + gid;
                    af[mi][0] = *(const uint32_t*)(a + rm * SAH + kb + 2 * t4);
                    af[mi][1] = *(const uint32_t*)(a + (rm + 8) * SAH + kb + 2 * t4);
                    af[mi][2] = *(const uint32_t*)(a + rm * SAH + kb + 8 + 2 * t4);
                    af[mi][3] = *(const uint32_t*)(a + (rm + 8) * SAH + kb + 8 + 2 * t4);
                }
                #pragma unroll
                for (int ni = 0; ni < 8; ni++) {
                    int n = wn * 64 + ni * 8 + gid;
                    bf[ni][0] = *(const uint32_t*)(b + n * SAH + kb + 2 * t4);
                    bf[ni][1] = *(const uint32_t*)(b + n * SAH + kb + 8 + 2 * t4);
                }
                #pragma unroll
                for (int mi = 0; mi < 2; mi++)
                    #pragma unroll
                    for (int ni = 0; ni < 8; ni++)
                        mma16(acc[mi][ni], af[mi], bf[ni]);
            }
        }
        __syncthreads();
    }

    // ---- epilogue: weighted atomic accumulate
    #pragma unroll
    for (int mi = 0; mi < 2; mi++) {
        int rb = row0 + wm * 32 + mi * 16 + gid;
        #pragma unroll
        for (int h = 0; h < 2; h++) {
            int r = rb + h * 8;
            if (r < cnt) {
                int   t = (z == 0) ? r : g_tok[e * T_ + r];
                float w = (z == 0) ? 1.f : g_wt[e * T_ + r];
                float* op = out + (size_t)t * H_ + col0 + wn * 64;
                #pragma unroll
                for (int ni = 0; ni < 8; ni++) {
                    int c = ni * 8 + t4 * 2;
                    atomicAdd(op + c,     w * acc[mi][ni][h * 2 + 0]);
                    atomicAdd(op + c + 1, w * acc[mi][ni][h * 2 + 1]);
                }
            }
        }
    }
}

// ---------------- launch ----------------
#define G1_SMEM ((2 * A_SZH + 4 * B64_SZH) * 2 + 768)
#define G2_SMEM ((2 * A_SZH + 2 * B128_SZH) * 2)

extern "C" void kernel_launch(void* const* d_in, const int* in_sizes, int n_in,
                              void* d_out, int out_size) {
    const float* x   = (const float*)d_in[0];
    const float* rw  = (const float*)d_in[1];
    const float* wg  = (const float*)d_in[2];
    const float* wu  = (const float*)d_in[3];
    const float* wd  = (const float*)d_in[4];
    const float* wgu = (const float*)d_in[5];
    const float* wsd = (const float*)d_in[6];

    cudaFuncSetAttribute(gemm1_mma, cudaFuncAttributeMaxDynamicSharedMemorySize, G1_SMEM);
    cudaFuncSetAttribute(gemm2_mma, cudaFuncAttributeMaxDynamicSharedMemorySize, G2_SMEM);

    cudaMemsetAsync(d_out, 0, (size_t)out_size * sizeof(float), 0);
    zero_counts_kernel<<<1, 32>>>();
    router_kernel<<<T_, 256>>>(x, rw);
    // z=0 = shared expert (largest K) scheduled first
    gemm1_mma<<<dim3(IS_ / 64, T_ / 128, E_ + 1), 256, G1_SMEM>>>(x, wg, wu, wgu);
    gemm2_mma<<<dim3(H_ / 128, T_ / 128, E_ + 1), 256, G2_SMEM>>>(wd, wsd, d_out ? (float*)d_out : nullptr);
}

// round 9
// speedup vs baseline: 1.2896x; 1.2896x over previous
#include <cuda_runtime.h>
#include <cuda_fp16.h>
#include <cstdint>

#define T_   1024
#define H_   1024
#define E_   16
#define I_   512      // MOE_INTER
#define IS_  1024     // SHARED_INTER
#define GUW_ 2048     // 2*SHARED_INTER

// ---------------- scratch (device globals; no allocs) ----------------
__device__ int    g_counts[E_];
__device__ int    g_tok[E_ * T_];
__device__ float  g_wt[E_ * T_];
__device__ __half g_h[(size_t)E_ * T_ * I_];    // routed intermediate (fp16)
__device__ __half g_hs[(size_t)T_ * IS_];       // shared-expert intermediate
__device__ __half g_xh[(size_t)T_ * H_];        // x in fp16
__device__ __half g_wgT[(size_t)E_ * I_ * H_];  // w_gate^T  [E][I][H]
__device__ __half g_wuT[(size_t)E_ * I_ * H_];  // w_up^T    [E][I][H]
__device__ __half g_wdT[(size_t)E_ * H_ * I_];  // w_down^T  [E][H][I]
__device__ __half g_wguT[(size_t)GUW_ * H_];    // ws_gate_up^T [2Is][H]
__device__ __half g_wsdT[(size_t)H_ * IS_];     // ws_down^T    [H][Is]

// ---------------- helpers ----------------
__device__ __forceinline__ float silu_mul(float g, float u) {
    return (g / (1.f + __expf(-g))) * u;
}
__device__ __forceinline__ uint32_t smem_u32(const void* p) {
    uint32_t a;
    asm("{ .reg .u64 t; cvta.to.shared.u64 t, %1; cvt.u32.u64 %0, t; }" : "=r"(a) : "l"(p));
    return a;
}
// m16n8k16 fp16 MMA, fp32 accum
__device__ __forceinline__ void mma16(float* d, const uint32_t* a, const uint32_t* b) {
    asm volatile(
        "mma.sync.aligned.m16n8k16.row.col.f32.f16.f16.f32 "
        "{%0,%1,%2,%3}, {%4,%5,%6,%7}, {%8,%9}, {%0,%1,%2,%3};"
        : "+f"(d[0]), "+f"(d[1]), "+f"(d[2]), "+f"(d[3])
        : "r"(a[0]), "r"(a[1]), "r"(a[2]), "r"(a[3]), "r"(b[0]), "r"(b[1]));
}
#define CP16(dst, src) asm volatile("cp.async.ca.shared.global [%0], [%1], 16;" :: "r"(dst), "l"(src))
#define CP_COMMIT()    asm volatile("cp.async.commit_group;" ::: "memory")
#define CP_WAIT2()     asm volatile("cp.async.wait_group 2;" ::: "memory")

#define SAH      40                      // smem row stride (halves), conflict-free
#define A_H      (128 * SAH)             // A part of a stage (halves)
#define STAGE_H  (256 * SAH)             // A+B stage (halves)
#define STAGE_B  (STAGE_H * 2)           // stage bytes
#define NSTG     4
#define GEMM_SMEM (NSTG * STAGE_B + 1024)

// ---------------- pre-pass: conversions ----------------
__global__ void conv_x_kernel(const float* __restrict__ x) {
    int i = (blockIdx.x * 256 + threadIdx.x) * 4;
    float4 v = *(const float4*)(x + i);
    __half2 a = __floats2half2_rn(v.x, v.y), b = __floats2half2_rn(v.z, v.w);
    *(uint2*)(g_xh + i) = make_uint2(*(uint32_t*)&a, *(uint32_t*)&b);
}

// [R,C] fp32 row-major -> [C,R] fp16 row-major, per-matrix (blockIdx.z)
__global__ void transpose_f2h(const float* __restrict__ in, __half* __restrict__ out,
                              int R, int C) {
    __shared__ float tile[32][33];
    size_t mo = (size_t)blockIdx.z * R * C;
    in += mo; out += mo;
    int c0 = blockIdx.x * 32, r0 = blockIdx.y * 32;
    int tx = threadIdx.x & 31, ty = threadIdx.x >> 5;      // 256 threads: ty 0..7
    #pragma unroll
    for (int i = 0; i < 32; i += 8)
        tile[ty + i][tx] = in[(size_t)(r0 + ty + i) * C + c0 + tx];
    __syncthreads();
    #pragma unroll
    for (int i = 0; i < 32; i += 8)
        out[(size_t)(c0 + ty + i) * R + r0 + tx] = __float2half_rn(tile[tx][ty + i]);
}

// ---------------- router ----------------
__global__ void zero_counts_kernel() {
    if (threadIdx.x < E_) g_counts[threadIdx.x] = 0;
}

__global__ void router_kernel(const float* __restrict__ x,
                              const float* __restrict__ rw) {
    __shared__ float sx[H_];
    __shared__ float slog[E_];
    int t = blockIdx.x;
    for (int i = threadIdx.x; i < H_; i += blockDim.x) sx[i] = x[(size_t)t * H_ + i];
    __syncthreads();
    int e = threadIdx.x >> 4, lane = threadIdx.x & 15;
    float s = 0.f;
    const float* w = rw + (size_t)e * H_;
    for (int i = lane; i < H_; i += 16) s += sx[i] * w[i];
    #pragma unroll
    for (int off = 8; off; off >>= 1) s += __shfl_down_sync(0xffffffffu, s, off, 16);
    if (lane == 0) slog[e] = s;
    __syncthreads();
    if (threadIdx.x == 0) {
        float l[E_];
        #pragma unroll
        for (int i = 0; i < E_; i++) l[i] = slog[i];
        int idx[4]; float lv[4]; bool used[E_];
        #pragma unroll
        for (int i = 0; i < E_; i++) used[i] = false;
        for (int k = 0; k < 4; k++) {      // top-4 of logits == top-4 of probs
            int bi = -1; float bv = -1e30f;
            for (int i = 0; i < E_; i++)
                if (!used[i] && l[i] > bv) { bv = l[i]; bi = i; }
            used[bi] = true; idx[k] = bi; lv[k] = bv;
        }
        float m = lv[0], ws[4], sum = 0.f;  // softmax denom cancels under top-k norm
        for (int k = 0; k < 4; k++) { ws[k] = __expf(lv[k] - m); sum += ws[k]; }
        float inv = 1.f / sum;
        for (int k = 0; k < 4; k++) {
            int pos = atomicAdd(&g_counts[idx[k]], 1);
            g_tok[idx[k] * T_ + pos] = t;
            g_wt[idx[k] * T_ + pos]  = ws[k] * inv;
        }
    }
}

// =====================================================================
// GEMM1: h = silu(A Wg) * (A Wu); all-fp16 cp.async pipeline
// BM=128 tokens, 128 B-rows = 64 (g,u) interleaved pairs, BK=32, 8 warps
// =====================================================================
__global__ __launch_bounds__(256)
void gemm1_mma() {
    extern __shared__ __half sh[];
    int z = blockIdx.z, cx = blockIdx.x, row0 = blockIdx.y * 128;
    int c0i = cx * 64;

    int cnt, e; const __half *bg, *bu; __half* hout; int ldo;
    if (z == 0) {
        e = -1; cnt = T_;
        bg = g_wguT + (size_t)c0i * H_;
        bu = g_wguT + (size_t)(IS_ + c0i) * H_;
        hout = g_hs + c0i; ldo = IS_;
    } else {
        e = z - 1;
        if (cx >= I_ / 64) return;
        cnt = g_counts[e];
        if (row0 >= cnt) return;
        bg = g_wgT + ((size_t)e * I_ + c0i) * H_;
        bu = g_wuT + ((size_t)e * I_ + c0i) * H_;
        hout = g_h + (size_t)e * T_ * I_ + c0i; ldo = I_;
    }
    if (row0 >= cnt) return;

    int* rows_s = (int*)(sh + NSTG * STAGE_H);
    int tid = threadIdx.x;
    if (tid < 128) {
        int r = row0 + tid;
        rows_s[tid] = (z == 0) ? r : ((r < cnt) ? g_tok[e * T_ + r] : -1);
    }
    __syncthreads();

    uint32_t smb = smem_u32(sh);
    // loader role: tid<128 -> A row tid; tid>=128 -> B row tid-128
    uint32_t dst_off;
    const __half* src;
    if (tid < 128) {
        int tr = rows_s[tid];
        dst_off = (uint32_t)tid * (SAH * 2);
        src = g_xh + (size_t)(tr < 0 ? 0 : tr) * H_;
    } else {
        int n = tid - 128, j = n >> 1;
        dst_off = (uint32_t)(A_H + n * SAH) * 2;
        src = ((n & 1) ? bu : bg) + (size_t)j * H_;
    }

    int lane = tid & 31, wid = tid >> 5, gid = lane >> 2, t4 = lane & 3;
    int wm = wid & 3, wn = wid >> 2;
    float acc[2][8][4] = {};

    const int NIT = H_ / 32;
    #pragma unroll 1
    for (int p = 0; p < 3; p++) {
        uint32_t d = smb + (uint32_t)p * STAGE_B + dst_off;
        const __half* s = src + p * 32;
        CP16(d, s); CP16(d + 16, s + 8); CP16(d + 32, s + 16); CP16(d + 48, s + 24);
        CP_COMMIT();
    }
    for (int it = 0; it < NIT; ++it) {
        CP_WAIT2();
        __syncthreads();
        if (it + 3 < NIT) {
            int st = (it + 3) & (NSTG - 1);
            uint32_t d = smb + (uint32_t)st * STAGE_B + dst_off;
            const __half* s = src + (it + 3) * 32;
            CP16(d, s); CP16(d + 16, s + 8); CP16(d + 32, s + 16); CP16(d + 48, s + 24);
            CP_COMMIT();
        }
        const __half* a = sh + (size_t)(it & (NSTG - 1)) * STAGE_H;
        const __half* b = a + A_H;
        #pragma unroll
        for (int kb = 0; kb < 32; kb += 16) {
            uint32_t af[2][4], bf[8][2];
            #pragma unroll
            for (int mi = 0; mi < 2; mi++) {
                int rm = wm * 32 + mi * 16 + gid;
                af[mi][0] = *(const uint32_t*)(a + rm * SAH + kb + 2 * t4);
                af[mi][1] = *(const uint32_t*)(a + (rm + 8) * SAH + kb + 2 * t4);
                af[mi][2] = *(const uint32_t*)(a + rm * SAH + kb + 8 + 2 * t4);
                af[mi][3] = *(const uint32_t*)(a + (rm + 8) * SAH + kb + 8 + 2 * t4);
            }
            #pragma unroll
            for (int ni = 0; ni < 8; ni++) {
                int n = wn * 64 + ni * 8 + gid;
                bf[ni][0] = *(const uint32_t*)(b + n * SAH + kb + 2 * t4);
                bf[ni][1] = *(const uint32_t*)(b + n * SAH + kb + 8 + 2 * t4);
            }
            #pragma unroll
            for (int mi = 0; mi < 2; mi++)
                #pragma unroll
                for (int ni = 0; ni < 8; ni++)
                    mma16(acc[mi][ni], af[mi], bf[ni]);
        }
        __syncthreads();
    }

    // epilogue: (d0,d1)=(g,u) pair for col j = wn*32 + ni*4 + t4
    #pragma unroll
    for (int mi = 0; mi < 2; mi++) {
        #pragma unroll
        for (int ni = 0; ni < 8; ni++) {
            int rb = row0 + wm * 32 + mi * 16 + gid;
            int j  = wn * 32 + ni * 4 + t4;
            if (rb < cnt)
                hout[(size_t)rb * ldo + j] =
                    __float2half_rn(silu_mul(acc[mi][ni][0], acc[mi][ni][1]));
            if (rb + 8 < cnt)
                hout[(size_t)(rb + 8) * ldo + j] =
                    __float2half_rn(silu_mul(acc[mi][ni][2], acc[mi][ni][3]));
        }
    }
}

// =====================================================================
// GEMM2: out += w * (h Wdown); all-fp16 cp.async pipeline
// BM=128, BN=128, BK=32, 8 warps, warp tile 32x64
// =====================================================================
__global__ __launch_bounds__(256)
void gemm2_mma(float* __restrict__ out) {
    extern __shared__ __half sh[];
    int z = blockIdx.z, col0 = blockIdx.x * 128, row0 = blockIdx.y * 128;

    int cnt, e, K; const __half *Ap, *Bp;
    if (z == 0) {
        e = -1; cnt = T_; K = IS_;
        Ap = g_hs;
        Bp = g_wsdT + (size_t)col0 * IS_;
    } else {
        e = z - 1; cnt = g_counts[e]; K = I_;
        if (row0 >= cnt) return;
        Ap = g_h + (size_t)e * T_ * I_;
        Bp = g_wdT + ((size_t)e * H_ + col0) * I_;
    }
    if (row0 >= cnt) return;

    uint32_t smb = smem_u32(sh);
    int tid = threadIdx.x;
    uint32_t dst_off;
    const __half* src;
    if (tid < 128) {
        int r = row0 + tid;
        if (r >= cnt) r = row0;          // clamp; result discarded
        dst_off = (uint32_t)tid * (SAH * 2);
        src = Ap + (size_t)r * K;
    } else {
        int n = tid - 128;
        dst_off = (uint32_t)(A_H + n * SAH) * 2;
        src = Bp + (size_t)n * K;
    }

    int lane = tid & 31, wid = tid >> 5, gid = lane >> 2, t4 = lane & 3;
    int wm = wid & 3, wn = wid >> 2;
    float acc[2][8][4] = {};

    const int NIT = K / 32;
    #pragma unroll 1
    for (int p = 0; p < 3; p++) {
        uint32_t d = smb + (uint32_t)p * STAGE_B + dst_off;
        const __half* s = src + p * 32;
        CP16(d, s); CP16(d + 16, s + 8); CP16(d + 32, s + 16); CP16(d + 48, s + 24);
        CP_COMMIT();
    }
    for (int it = 0; it < NIT; ++it) {
        CP_WAIT2();
        __syncthreads();
        if (it + 3 < NIT) {
            int st = (it + 3) & (NSTG - 1);
            uint32_t d = smb + (uint32_t)st * STAGE_B + dst_off;
            const __half* s = src + (it + 3) * 32;
            CP16(d, s); CP16(d + 16, s + 8); CP16(d + 32, s + 16); CP16(d + 48, s + 24);
            CP_COMMIT();
        }
        const __half* a = sh + (size_t)(it & (NSTG - 1)) * STAGE_H;
        const __half* b = a + A_H;
        #pragma unroll
        for (int kb = 0; kb < 32; kb += 16) {
            uint32_t af[2][4], bf[8][2];
            #pragma unroll
            for (int mi = 0; mi < 2; mi++) {
                int rm = wm * 32 + mi * 16 + gid;
                af[mi][0] = *(const uint32_t*)(a + rm * SAH + kb + 2 * t4);
                af[mi][1] = *(const uint32_t*)(a + (rm + 8) * SAH + kb + 2 * t4);
                af[mi][2] = *(const uint32_t*)(a + rm * SAH + kb + 8 + 2 * t4);
                af[mi][3] = *(const uint32_t*)(a + (rm + 8) * SAH + kb + 8 + 2 * t4);
            }
            #pragma unroll
            for (int ni = 0; ni < 8; ni++) {
                int n = wn * 64 + ni * 8 + gid;
                bf[ni][0] = *(const uint32_t*)(b + n * SAH + kb + 2 * t4);
                bf[ni][1] = *(const uint32_t*)(b + n * SAH + kb + 8 + 2 * t4);
            }
            #pragma unroll
            for (int mi = 0; mi < 2; mi++)
                #pragma unroll
                for (int ni = 0; ni < 8; ni++)
                    mma16(acc[mi][ni], af[mi], bf[ni]);
        }
        __syncthreads();
    }

    // epilogue: weighted atomic accumulate
    #pragma unroll
    for (int mi = 0; mi < 2; mi++) {
        int rb = row0 + wm * 32 + mi * 16 + gid;
        #pragma unroll
        for (int h = 0; h < 2; h++) {
            int r = rb + h * 8;
            if (r < cnt) {
                int   t = (z == 0) ? r : g_tok[e * T_ + r];
                float w = (z == 0) ? 1.f : g_wt[e * T_ + r];
                float* op = out + (size_t)t * H_ + col0 + wn * 64;
                #pragma unroll
                for (int ni = 0; ni < 8; ni++) {
                    int c = ni * 8 + t4 * 2;
                    atomicAdd(op + c,     w * acc[mi][ni][h * 2 + 0]);
                    atomicAdd(op + c + 1, w * acc[mi][ni][h * 2 + 1]);
                }
            }
        }
    }
}

// ---------------- launch ----------------
extern "C" void kernel_launch(void* const* d_in, const int* in_sizes, int n_in,
                              void* d_out, int out_size) {
    const float* x   = (const float*)d_in[0];
    const float* rw  = (const float*)d_in[1];
    const float* wg  = (const float*)d_in[2];
    const float* wu  = (const float*)d_in[3];
    const float* wd  = (const float*)d_in[4];
    const float* wgu = (const float*)d_in[5];
    const float* wsd = (const float*)d_in[6];

    void *pwgT, *pwuT, *pwdT, *pwguT, *pwsdT;
    cudaGetSymbolAddress(&pwgT,  g_wgT);
    cudaGetSymbolAddress(&pwuT,  g_wuT);
    cudaGetSymbolAddress(&pwdT,  g_wdT);
    cudaGetSymbolAddress(&pwguT, g_wguT);
    cudaGetSymbolAddress(&pwsdT, g_wsdT);

    cudaFuncSetAttribute(gemm1_mma, cudaFuncAttributeMaxDynamicSharedMemorySize, GEMM_SMEM);
    cudaFuncSetAttribute(gemm2_mma, cudaFuncAttributeMaxDynamicSharedMemorySize, GEMM_SMEM);

    cudaMemsetAsync(d_out, 0, (size_t)out_size * sizeof(float), 0);
    zero_counts_kernel<<<1, 32>>>();
    router_kernel<<<T_, 256>>>(x, rw);

    conv_x_kernel<<<T_ * H_ / 1024, 256>>>(x);
    transpose_f2h<<<dim3(I_ / 32,  H_ / 32,  E_), 256>>>(wg,  (__half*)pwgT,  H_,  I_);
    transpose_f2h<<<dim3(I_ / 32,  H_ / 32,  E_), 256>>>(wu,  (__half*)pwuT,  H_,  I_);
    transpose_f2h<<<dim3(H_ / 32,  I_ / 32,  E_), 256>>>(wd,  (__half*)pwdT,  I_,  H_);
    transpose_f2h<<<dim3(GUW_ / 32, H_ / 32, 1),  256>>>(wgu, (__half*)pwguT, H_,  GUW_);
    transpose_f2h<<<dim3(H_ / 32,  IS_ / 32, 1),  256>>>(wsd, (__half*)pwsdT, IS_, H_);

    // z=0 = shared expert (largest K) scheduled first
    gemm1_mma<<<dim3(IS_ / 64, T_ / 128, E_ + 1), 256, GEMM_SMEM>>>();
    gemm2_mma<<<dim3(H_ / 128, T_ / 128, E_ + 1), 256, GEMM_SMEM>>>((float*)d_out);
}